// round 4
// baseline (speedup 1.0000x reference)
#include <cuda_runtime.h>
#include <math.h>

#define S_LEN    4096
#define LC       16
#define CHAR_DIM 64
#define CHAR_H   128
#define N_DIM    256
#define NH       512
#define N_TAG    64
#define FEAT     384      // N_DIM + CHAR_H
#define G4       2048     // 4*NH
#define CG4      512      // 4*CHAR_H
#define NB_WORD  128      // CTAs in persistent word-recurrence kernel

// ---------------- scratch (static device globals; no allocation) ----------------
__device__ float g_charH0[S_LEN * CHAR_H];
__device__ float g_charH1[S_LEN * CHAR_H];
__device__ float g_charC [S_LEN * CHAR_H];
__device__ float g_Gin   [S_LEN * G4];     // word-LSTM input preactivations (+biases)
__device__ float g_hs    [S_LEN * NH];     // word-LSTM hidden outputs, all steps
__device__ int   g_done  [S_LEN];          // per-step completion counters

__device__ __forceinline__ float sigf(float x) { return 1.f / (1.f + expf(-x)); }

// ---------------- init: zero recurrent state + sync counters ----------------
__global__ void k_init()
{
    int i = blockIdx.x * blockDim.x + threadIdx.x;
    int stride = gridDim.x * blockDim.x;
    for (int j = i; j < S_LEN * CHAR_H; j += stride) {
        g_charH0[j] = 0.f;
        g_charC[j]  = 0.f;
    }
    for (int j = i; j < S_LEN; j += stride) g_done[j] = 0;
}

// ---------------- char LSTM: one time step, fused GEMM + gates ----------------
// Block (bw, bh): 64 words x 16 h-dims. Computes G[64 x 64] where virtual col
// n -> gate = n>>4, hh = hh0 + (n&15); K = 192 = [emb(64) | H(128)].
__global__ void k_char_step(const float* __restrict__ ce,
                            const float* __restrict__ Wih,
                            const float* __restrict__ Whh,
                            const float* __restrict__ bih,
                            const float* __restrict__ bhh,
                            const int*   __restrict__ chars,
                            const int*   __restrict__ lens,
                            int t)
{
    __shared__ float As[32 * 65];
    __shared__ float Bs[32 * 65];
    __shared__ float Gs[64 * 65];
    __shared__ int   cidx[64];

    const int w0  = blockIdx.x * 64;
    const int hh0 = blockIdx.y * 16;
    const int tid = threadIdx.x;

    const float* Hin  = (t & 1) ? g_charH1 : g_charH0;
    float*       Hout = (t & 1) ? g_charH0 : g_charH1;

    if (tid < 64) cidx[tid] = chars[(w0 + tid) * LC + t];
    __syncthreads();

    const int ty = tid >> 4, tx = tid & 15;
    float acc[4][4];
#pragma unroll
    for (int i = 0; i < 4; i++)
#pragma unroll
        for (int j = 0; j < 4; j++) acc[i][j] = 0.f;

    for (int k0 = 0; k0 < 192; k0 += 32) {
#pragma unroll
        for (int e = tid; e < 2048; e += 256) {
            const int k = e & 31, q = e >> 5;   // q = word idx (A) / col idx (B)
            const int kg = k0 + k;
            float av, bv;
            if (kg < CHAR_DIM) av = ce[cidx[q] * CHAR_DIM + kg];
            else               av = Hin[(w0 + q) * CHAR_H + (kg - CHAR_DIM)];
            const int col = (q >> 4) * CHAR_H + hh0 + (q & 15);
            if (kg < CHAR_DIM) bv = Wih[col * CHAR_DIM + kg];
            else               bv = Whh[col * CHAR_H + (kg - CHAR_DIM)];
            As[k * 65 + q] = av;
            Bs[k * 65 + q] = bv;
        }
        __syncthreads();
#pragma unroll
        for (int kk = 0; kk < 32; kk++) {
            float a[4], bb[4];
#pragma unroll
            for (int i = 0; i < 4; i++) a[i]  = As[kk * 65 + ty * 4 + i];
#pragma unroll
            for (int j = 0; j < 4; j++) bb[j] = Bs[kk * 65 + tx * 4 + j];
#pragma unroll
            for (int i = 0; i < 4; i++)
#pragma unroll
                for (int j = 0; j < 4; j++) acc[i][j] = fmaf(a[i], bb[j], acc[i][j]);
        }
        __syncthreads();
    }

#pragma unroll
    for (int i = 0; i < 4; i++)
#pragma unroll
        for (int j = 0; j < 4; j++) Gs[(ty * 4 + i) * 65 + tx * 4 + j] = acc[i][j];
    __syncthreads();

    // gate epilogue: 64 words x 16 hh = 1024 items
    for (int it = tid; it < 1024; it += 256) {
        const int wi = it >> 4, hi = it & 15;
        const int w = w0 + wi, hh = hh0 + hi;
        float gi = Gs[wi * 65 + hi]      + bih[hh]              + bhh[hh];
        float gf = Gs[wi * 65 + 16 + hi] + bih[CHAR_H + hh]     + bhh[CHAR_H + hh];
        float gg = Gs[wi * 65 + 32 + hi] + bih[2 * CHAR_H + hh] + bhh[2 * CHAR_H + hh];
        float go = Gs[wi * 65 + 48 + hi] + bih[3 * CHAR_H + hh] + bhh[3 * CHAR_H + hh];
        float c_old = g_charC[w * CHAR_H + hh];
        float h_old = Hin[w * CHAR_H + hh];
        float cn = sigf(gf) * c_old + sigf(gi) * tanhf(gg);
        float hn = sigf(go) * tanhf(cn);
        if (t < lens[w]) {
            g_charC[w * CHAR_H + hh] = cn;
            Hout[w * CHAR_H + hh]    = hn;
        } else {
            Hout[w * CHAR_H + hh]    = h_old;
        }
    }
}

// ---------------- word-LSTM input preactivations: Gin = feat @ Wih^T + bih + bhh ----
// GEMM M=4096, N=2048, K=384, A = [word_emb[x[w]] | charH(final)]
__global__ void k_gin(const float* __restrict__ wemb,
                      const float* __restrict__ Wih,
                      const float* __restrict__ bih,
                      const float* __restrict__ bhh,
                      const int*   __restrict__ x)
{
    __shared__ float As[32 * 65];
    __shared__ float Bs[32 * 65];
    __shared__ int   widx[64];

    const int w0 = blockIdx.x * 64;
    const int n0 = blockIdx.y * 64;
    const int tid = threadIdx.x;

    if (tid < 64) widx[tid] = x[w0 + tid];
    __syncthreads();

    const int ty = tid >> 4, tx = tid & 15;
    float acc[4][4];
#pragma unroll
    for (int i = 0; i < 4; i++)
#pragma unroll
        for (int j = 0; j < 4; j++) acc[i][j] = 0.f;

    for (int k0 = 0; k0 < FEAT; k0 += 32) {
#pragma unroll
        for (int e = tid; e < 2048; e += 256) {
            const int k = e & 31, q = e >> 5;
            const int kg = k0 + k;
            float av;
            if (kg < N_DIM) av = wemb[widx[q] * N_DIM + kg];
            else            av = g_charH0[(w0 + q) * CHAR_H + (kg - N_DIM)];
            As[k * 65 + q] = av;
            Bs[k * 65 + q] = Wih[(n0 + q) * FEAT + kg];
        }
        __syncthreads();
#pragma unroll
        for (int kk = 0; kk < 32; kk++) {
            float a[4], bb[4];
#pragma unroll
            for (int i = 0; i < 4; i++) a[i]  = As[kk * 65 + ty * 4 + i];
#pragma unroll
            for (int j = 0; j < 4; j++) bb[j] = Bs[kk * 65 + tx * 4 + j];
#pragma unroll
            for (int i = 0; i < 4; i++)
#pragma unroll
                for (int j = 0; j < 4; j++) acc[i][j] = fmaf(a[i], bb[j], acc[i][j]);
        }
        __syncthreads();
    }

#pragma unroll
    for (int i = 0; i < 4; i++) {
        const int w = w0 + ty * 4 + i;
#pragma unroll
        for (int j = 0; j < 4; j++) {
            const int n = n0 + tx * 4 + j;
            g_Gin[w * G4 + n] = acc[i][j] + bih[n] + bhh[n];
        }
    }
}

// ---------------- word-LSTM recurrence: persistent, 128 CTAs, spin sync ----------
// CTA b owns h-dims j0 = 4b..4b+3 (16 gate rows). Weights cached in smem.
// Sync: writers fence + atomicAdd(g_done[t]); readers volatile-poll g_done[t-1]==128.
__global__ void __launch_bounds__(256) k_word(const float* __restrict__ Whh)
{
    __shared__ float ws[16 * NH];    // 32 KB: this CTA's 16 gate rows
    __shared__ float hprev[NH];
    __shared__ float gatev[16];
    __shared__ float cbuf[4];

    const int b   = blockIdx.x;
    const int tid = threadIdx.x;
    const int j0  = b * 4;
    const int lr  = tid >> 4;        // 0..15: gate = lr>>2, jj = lr&3
    const int sub = tid & 15;
    const int grow = (lr >> 2) * NH + j0 + (lr & 3);

    for (int e = tid; e < 16 * NH; e += 256) {
        const int r = e >> 9, k = e & (NH - 1);
        const int gr = (r >> 2) * NH + j0 + (r & 3);
        ws[r * NH + k] = Whh[gr * NH + k];
    }
    if (tid < 4) cbuf[tid] = 0.f;
    volatile int* vdone = (volatile int*)g_done;
    __syncthreads();

    for (int t = 0; t < S_LEN; t++) {
        float ginv = 0.f;
        if (sub == 0) ginv = g_Gin[t * G4 + grow];   // issued before the wait
        float p = 0.f;
        if (t > 0) {
            if (tid == 0) { while (vdone[t - 1] < NB_WORD) { } }
            __syncthreads();
            hprev[tid]       = g_hs[(t - 1) * NH + tid];
            hprev[tid + 256] = g_hs[(t - 1) * NH + 256 + tid];
            __syncthreads();
            const float* wrow = ws + lr * NH;
#pragma unroll
            for (int k = 0; k < 32; k++)
                p = fmaf(wrow[k * 16 + sub], hprev[k * 16 + sub], p);
        }
        p += __shfl_down_sync(0xffffffffu, p, 8, 16);
        p += __shfl_down_sync(0xffffffffu, p, 4, 16);
        p += __shfl_down_sync(0xffffffffu, p, 2, 16);
        p += __shfl_down_sync(0xffffffffu, p, 1, 16);
        if (sub == 0) gatev[lr] = p + ginv;
        __syncthreads();
        if (tid < 4) {
            float gi = gatev[tid], gf = gatev[4 + tid];
            float gg = gatev[8 + tid], go = gatev[12 + tid];
            float cn = sigf(gf) * cbuf[tid] + sigf(gi) * tanhf(gg);
            cbuf[tid] = cn;
            g_hs[t * NH + j0 + tid] = sigf(go) * tanhf(cn);
            __threadfence();
        }
        __syncthreads();
        if (tid == 0) atomicAdd(&g_done[t], 1);
    }
}

// ---------------- logits + log_softmax ----------------
__global__ void k_logits(const float* __restrict__ W1,
                         const float* __restrict__ b1,
                         float* __restrict__ out)
{
    __shared__ float hsh[NH];
    __shared__ float sv[N_TAG];
    const int w = blockIdx.x;
    const int n = threadIdx.x;

    for (int k = n; k < NH; k += N_TAG) hsh[k] = g_hs[w * NH + k];
    __syncthreads();

    const float4* wr = (const float4*)(W1 + n * NH);
    float acc = b1[n];
#pragma unroll 8
    for (int k4 = 0; k4 < NH / 4; k4++) {
        float4 v = wr[k4];
        acc += v.x * hsh[k4 * 4]     + v.y * hsh[k4 * 4 + 1]
             + v.z * hsh[k4 * 4 + 2] + v.w * hsh[k4 * 4 + 3];
    }
    sv[n] = acc;
    __syncthreads();
    float mx = -1e30f;
    for (int i = 0; i < N_TAG; i++) mx = fmaxf(mx, sv[i]);
    float se = 0.f;
    for (int i = 0; i < N_TAG; i++) se += expf(sv[i] - mx);
    out[w * N_TAG + n] = acc - mx - logf(se);
}

// ---------------- launch ----------------
extern "C" void kernel_launch(void* const* d_in, const int* in_sizes, int n_in,
                              void* d_out, int out_size)
{
    const float* char_emb = (const float*)d_in[0];
    const float* char_Wih = (const float*)d_in[1];
    const float* char_Whh = (const float*)d_in[2];
    const float* char_bih = (const float*)d_in[3];
    const float* char_bhh = (const float*)d_in[4];
    const float* word_emb = (const float*)d_in[5];
    const float* Wih      = (const float*)d_in[6];
    const float* Whh      = (const float*)d_in[7];
    const float* bih      = (const float*)d_in[8];
    const float* bhh      = (const float*)d_in[9];
    const float* W1       = (const float*)d_in[10];
    const float* b1       = (const float*)d_in[11];
    const int*   x        = (const int*)d_in[12];
    const int*   chars    = (const int*)d_in[13];
    const int*   lens     = (const int*)d_in[14];
    float* out = (float*)d_out;

    k_init<<<256, 256>>>();
    for (int t = 0; t < LC; t++)
        k_char_step<<<dim3(64, 8), 256>>>(char_emb, char_Wih, char_Whh,
                                          char_bih, char_bhh, chars, lens, t);
    k_gin<<<dim3(64, 32), 256>>>(word_emb, Wih, bih, bhh, x);
    k_word<<<NB_WORD, 256>>>(Whh);
    k_logits<<<S_LEN, N_TAG>>>(W1, b1, out);
}